// round 1
// baseline (speedup 1.0000x reference)
#include <cuda_runtime.h>
#include <cuda_bf16.h>
#include <cstdint>

// Problem shape (fixed by the dataset)
#define VOCAB 2048
#define HID   1024
#define TT    256
#define BB    128
#define BH    (BB * HID)            // 131072 elems per timestep of Y

// Scratch: Y[t, b, h]  (t*B+b row-major => exactly the decoder's input matrix)
__device__ float g_Y[(size_t)TT * BH];   // 134 MB, static device scratch (allowed)

// ---------------- f32x2 helpers (FFMA2: 2 MACs per issue) ----------------
__device__ __forceinline__ unsigned long long f32x2_pack(float lo, float hi) {
    unsigned long long r;
    asm("mov.b64 %0, {%1, %2};" : "=l"(r) : "f"(lo), "f"(hi));
    return r;
}
__device__ __forceinline__ unsigned long long f32x2_fma(unsigned long long a,
                                                        unsigned long long b,
                                                        unsigned long long c) {
    unsigned long long d;
    asm("fma.rn.f32x2 %0, %1, %2, %3;" : "=l"(d) : "l"(a), "l"(b), "l"(c));
    return d;
}
__device__ __forceinline__ void f32x2_unpack(unsigned long long v, float& lo, float& hi) {
    asm("mov.b64 {%0, %1}, %2;" : "=f"(lo), "=f"(hi) : "l"(v));
}

// =====================================================================
// Recurrence step:  h_t = tanh( Wx[idx[:,t]] + h_{t-1} @ Wh + b )
// Tile: BM=32 (batch rows), BN=32 (hidden cols), BK=32. 256 threads.
// Each thread: 1 row x 4 cols (2 f32x2 accumulators).
// Grid: (128/32, 1024/32) = (4, 32) = 128 blocks.
// Reads h_{t-1} from g_Y (or initial state at t==0), writes g_Y[t].
// =====================================================================
__global__ void __launch_bounds__(256, 4)
rnn_step_kernel(const float* __restrict__ state,
                const int*   __restrict__ inputs,   // [B, T] int32
                const float* __restrict__ Wx,       // [VOCAB, HID]
                const float* __restrict__ Wh,       // [HID, HID]
                const float* __restrict__ bias,     // [HID]
                int t)
{
    __shared__ float As[32][33];   // h tile, transposed: As[k][m]
    __shared__ float Bs[32][36];   // Wh tile: Bs[k][n]   (pad 36 keeps 16B align)

    const int tid = threadIdx.x;
    const int m0  = blockIdx.x * 32;
    const int n0  = blockIdx.y * 32;

    const int ty = tid >> 3;        // row within tile: 0..31
    const int tx = tid & 7;         // col group: cols tx*4 .. tx*4+3

    const float* __restrict__ hprev =
        (t == 0) ? state : (g_Y + (size_t)(t - 1) * BH);
    float* __restrict__ hout = g_Y + (size_t)t * BH;

    unsigned long long acc0 = 0ull, acc1 = 0ull;   // {0.f,0.f} bit pattern

    const int lm  = tid >> 3;          // 0..31  (row for A load / row for B load)
    const int lk4 = (tid & 7) * 4;     // 0..28  (k/n quad offset)

    for (int k0 = 0; k0 < HID; k0 += 32) {
        // Load h tile (32 rows x 32 k), transpose into As[k][m]
        float4 va = *(const float4*)&hprev[(size_t)(m0 + lm) * HID + k0 + lk4];
        As[lk4 + 0][lm] = va.x;
        As[lk4 + 1][lm] = va.y;
        As[lk4 + 2][lm] = va.z;
        As[lk4 + 3][lm] = va.w;
        // Load Wh tile (32 k x 32 n)
        *(float4*)&Bs[lm][lk4] =
            *(const float4*)&Wh[(size_t)(k0 + lm) * HID + n0 + lk4];
        __syncthreads();

#pragma unroll
        for (int kk = 0; kk < 32; kk++) {
            float a = As[kk][ty];
            unsigned long long ap = f32x2_pack(a, a);
            ulonglong2 bv = *(const ulonglong2*)&Bs[kk][tx * 4];
            acc0 = f32x2_fma(ap, bv.x, acc0);
            acc1 = f32x2_fma(ap, bv.y, acc1);
        }
        __syncthreads();
    }

    // Epilogue: + Wx[token] + b, tanh, store to Y[t]
    const int m = m0 + ty;
    const int n = n0 + tx * 4;
    const int vrow = inputs[m * TT + t];           // inputs[b][t]
    const float* wxr = Wx + (size_t)vrow * HID + n;

    float c0, c1, c2, c3;
    f32x2_unpack(acc0, c0, c1);
    f32x2_unpack(acc1, c2, c3);

    float* o = hout + (size_t)m * HID + n;
    o[0] = tanhf(c0 + wxr[0] + bias[n + 0]);
    o[1] = tanhf(c1 + wxr[1] + bias[n + 1]);
    o[2] = tanhf(c2 + wxr[2] + bias[n + 2]);
    o[3] = tanhf(c3 + wxr[3] + bias[n + 3]);
}

// =====================================================================
// Decoder:  out[r, v] = Y[r, :] @ Wd[:, v] + bd[v]
// r in [0, T*B) = 32768, v in [0, 2048), K = 1024.
// Tile: BM=64, BN=64, BK=16, 256 threads, 4x4 micro-tile (8 f32x2 accs).
// Grid: (2048/64, 32768/64) = (32, 512) = 16384 blocks.
// =====================================================================
__global__ void __launch_bounds__(256, 3)
decoder_kernel(const float* __restrict__ Wd,   // [HID, VOCAB]
               const float* __restrict__ bd,   // [VOCAB]
               float* __restrict__ out)        // [T*B, VOCAB]
{
    __shared__ float As[16][68];   // Y tile transposed: As[k][m]
    __shared__ float Bs[16][68];   // Wd tile: Bs[k][n]

    const int tid = threadIdx.x;
    const int n0  = blockIdx.x * 64;
    const int m0  = blockIdx.y * 64;

    const int tx = tid & 15;        // col group: cols tx*4..+3
    const int ty = tid >> 4;        // row group: rows ty*4..+3

    unsigned long long acc[4][2];
#pragma unroll
    for (int i = 0; i < 4; i++) { acc[i][0] = 0ull; acc[i][1] = 0ull; }

    const int am  = tid >> 2;            // 0..63   A-load row
    const int ak4 = (tid & 3) * 4;       // 0,4,8,12
    const int bk  = tid >> 4;            // 0..15   B-load k
    const int bn4 = (tid & 15) * 4;      // 0..60

    const float* __restrict__ Y = g_Y;   // (T*B, HID) row-major by construction

    for (int k0 = 0; k0 < HID; k0 += 16) {
        float4 va = *(const float4*)&Y[(size_t)(m0 + am) * HID + k0 + ak4];
        As[ak4 + 0][am] = va.x;
        As[ak4 + 1][am] = va.y;
        As[ak4 + 2][am] = va.z;
        As[ak4 + 3][am] = va.w;
        *(float4*)&Bs[bk][bn4] =
            *(const float4*)&Wd[(size_t)(k0 + bk) * VOCAB + n0 + bn4];
        __syncthreads();

#pragma unroll
        for (int kk = 0; kk < 16; kk++) {
            float4 av = *(const float4*)&As[kk][ty * 4];
            ulonglong2 bv = *(const ulonglong2*)&Bs[kk][tx * 4];
            unsigned long long a0 = f32x2_pack(av.x, av.x);
            unsigned long long a1 = f32x2_pack(av.y, av.y);
            unsigned long long a2 = f32x2_pack(av.z, av.z);
            unsigned long long a3 = f32x2_pack(av.w, av.w);
            acc[0][0] = f32x2_fma(a0, bv.x, acc[0][0]);
            acc[0][1] = f32x2_fma(a0, bv.y, acc[0][1]);
            acc[1][0] = f32x2_fma(a1, bv.x, acc[1][0]);
            acc[1][1] = f32x2_fma(a1, bv.y, acc[1][1]);
            acc[2][0] = f32x2_fma(a2, bv.x, acc[2][0]);
            acc[2][1] = f32x2_fma(a2, bv.y, acc[2][1]);
            acc[3][0] = f32x2_fma(a3, bv.x, acc[3][0]);
            acc[3][1] = f32x2_fma(a3, bv.y, acc[3][1]);
        }
        __syncthreads();
    }

    const int n = n0 + tx * 4;
    const float b0 = bd[n + 0], b1 = bd[n + 1], b2 = bd[n + 2], b3 = bd[n + 3];
#pragma unroll
    for (int i = 0; i < 4; i++) {
        const int r = m0 + ty * 4 + i;
        float c0, c1, c2, c3;
        f32x2_unpack(acc[i][0], c0, c1);
        f32x2_unpack(acc[i][1], c2, c3);
        float4 v = make_float4(c0 + b0, c1 + b1, c2 + b2, c3 + b3);
        *(float4*)&out[(size_t)r * VOCAB + n] = v;
    }
}

// Copy h_final = Y[T-1] into the tail of the output buffer.
__global__ void copy_hfinal_kernel(float* __restrict__ dst)
{
    int i = blockIdx.x * 256 + threadIdx.x;
    dst[i] = g_Y[(size_t)(TT - 1) * BH + i];
}

extern "C" void kernel_launch(void* const* d_in, const int* in_sizes, int n_in,
                              void* d_out, int out_size)
{
    const int*   inputs = (const int*)  d_in[0];   // (B, T) int32
    const float* state  = (const float*)d_in[1];   // (B, H)
    const float* Wx     = (const float*)d_in[2];   // (V, H)
    const float* Wh     = (const float*)d_in[3];   // (H, H)
    const float* bias   = (const float*)d_in[4];   // (H,)
    const float* Wd     = (const float*)d_in[5];   // (H, V)
    const float* bd     = (const float*)d_in[6];   // (V,)
    float* out = (float*)d_out;

    // Recurrence: 256 dependent GEMM launches (graph nodes)
    dim3 gridR(BB / 32, HID / 32);   // (4, 32)
    for (int t = 0; t < TT; t++) {
        rnn_step_kernel<<<gridR, 256>>>(state, inputs, Wx, Wh, bias, t);
    }

    // Decoder GEMM over all timesteps at once
    dim3 gridD(VOCAB / 64, (TT * BB) / 64);   // (32, 512)
    decoder_kernel<<<gridD, 256>>>(Wd, bd, out);

    // h_final at the tail of the flattened output tuple
    size_t hf_off = (size_t)out_size - (size_t)BB * HID;
    copy_hfinal_kernel<<<(BB * HID) / 256, 256>>>(out + hf_off);
}

// round 2
// speedup vs baseline: 1.7640x; 1.7640x over previous
#include <cuda_runtime.h>
#include <cstdint>

#define VOCAB 2048
#define HID   1024
#define TT    256
#define BB    128
#define NCTAS 128

// ---- persistent scratch (static device allocations are allowed) ----
__device__ float g_YT[(size_t)TT * HID * BB];  // [t][k][m]  128 MB (transposed Y)
__device__ float g_h0T[HID * BB];              // transposed initial state
__device__ float g_P[8u * HID * BB];           // k-split partials [g][n][m], 4 MB
__device__ unsigned g_cnt;                     // barrier arrival counter
__device__ unsigned g_phase;                   // barrier release phase

// ---------------- f32x2 helpers (FFMA2: 2 MACs per issue) ----------------
__device__ __forceinline__ unsigned long long f32x2_pack(float lo, float hi) {
    unsigned long long r;
    asm("mov.b64 %0, {%1, %2};" : "=l"(r) : "f"(lo), "f"(hi));
    return r;
}
__device__ __forceinline__ unsigned long long f32x2_fma(unsigned long long a,
                                                        unsigned long long b,
                                                        unsigned long long c) {
    unsigned long long d;
    asm("fma.rn.f32x2 %0, %1, %2, %3;" : "=l"(d) : "l"(a), "l"(b), "l"(c));
    return d;
}
__device__ __forceinline__ void f32x2_unpack(unsigned long long v, float& lo, float& hi) {
    asm("mov.b64 {%0, %1}, %2;" : "=f"(lo), "=f"(hi) : "l"(v));
}

// ---------------- grid barrier (128 CTAs, all resident) ----------------
__device__ __forceinline__ void grid_barrier(unsigned epoch) {
    __threadfence();                 // make this thread's stores gpu-visible
    __syncthreads();                 // everyone in the block arrived + fenced
    if (threadIdx.x == 0) {
        unsigned a = atomicAdd(&g_cnt, 1u);
        if (a == epoch * (unsigned)NCTAS - 1u) {
            asm volatile("st.release.gpu.u32 [%0], %1;"
                         :: "l"(&g_phase), "r"(epoch) : "memory");
        } else {
            unsigned cur;
            do {
                asm volatile("ld.acquire.gpu.u32 %0, [%1];"
                             : "=r"(cur) : "l"(&g_phase) : "memory");
                if (cur < epoch) __nanosleep(64);
            } while (cur < epoch);
        }
    }
    __syncthreads();
}

// ---------------- init: reset barrier + transpose initial state ----------------
__global__ void init_kernel(const float* __restrict__ state) {
    if (blockIdx.x == 0 && threadIdx.x == 0) { g_cnt = 0u; g_phase = 0u; }
    int idx = blockIdx.x * 256 + threadIdx.x;        // 131072 total
    int m = idx & (BB - 1);
    int k = idx >> 7;
    g_h0T[k * BB + m] = state[(size_t)m * HID + k];  // coalesced write
}

// =====================================================================
// Persistent recurrence:  hT_t = tanh( Wx[idx[:,t]] + Wh^T-applied + b )
// 128 CTAs x 256 threads. CTA (kg,cg): k-range kg*256, cols cg*32.
// Wh block (256k x 32n = 32KB) lives in SMEM for all 256 steps.
// Phase A: lane = batch row, 32-col f32x2 accumulators, h streamed
//          coalesced from L2 (__ldcg) in transposed layout.
// Phase B: reduce 8 k-partials + Wx gather + bias + tanh -> YT[t].
// =====================================================================
__global__ void __launch_bounds__(256, 1)
rnn_persistent(const int*   __restrict__ inputs,   // [B, T]
               const float* __restrict__ Wx,       // [V, H]
               const float* __restrict__ Wh,       // [H, H]
               const float* __restrict__ bias)     // [H]
{
    __shared__ float Whs[256][32];                 // [k-local][n-local]

    const int tid = threadIdx.x;
    const int cta = blockIdx.x;                    // 0..127
    const int cg  = cta & 31;                      // col group
    const int kg  = cta >> 5;                      // k group
    const int n0  = cg * 32;
    const int ks  = kg * 256;

    // Load the CTA's Wh block once (stays resident all 256 steps)
    for (int i = tid; i < 256 * 32; i += 256) {
        int kk = i >> 5, nn = i & 31;
        Whs[kk][nn] = Wh[(size_t)(ks + kk) * HID + n0 + nn];
    }
    __syncthreads();

    const int warp  = tid >> 5;
    const int lane  = tid & 31;
    const int mrow  = (warp & 3) * 32 + lane;      // batch row this lane owns
    const int khalf = warp >> 2;                   // 0/1
    const int g     = kg * 2 + khalf;              // partial group 0..7
    const int kloc0 = khalf * 128;                 // local k offset in Whs
    const int kbeg  = ks + kloc0;                  // global k offset

    // phase-B assignment: warp -> one hidden col, lane -> batch row
    const int nb    = cta * 8 + warp;              // 0..1023
    const float bv  = bias[nb];

    unsigned epoch = 0;

    for (int t = 0; t < TT; t++) {
        const float* __restrict__ hT =
            (t == 0) ? g_h0T : (g_YT + (size_t)(t - 1) * HID * BB);

        // ---------------- phase A: partial GEMM ----------------
        unsigned long long acc[16];
#pragma unroll
        for (int j = 0; j < 16; j++) acc[j] = 0ull;

        const float* __restrict__ hp = hT + (size_t)kbeg * BB + mrow;

#pragma unroll 4
        for (int k = 0; k < 128; k++) {
            float a = __ldcg(hp + (size_t)k * BB);          // coalesced, L2
            unsigned long long ap = f32x2_pack(a, a);
            const float* wr = &Whs[kloc0 + k][0];
#pragma unroll
            for (int q = 0; q < 8; q++) {
                ulonglong2 bb = *(const ulonglong2*)(wr + q * 4);  // broadcast
                acc[2 * q]     = f32x2_fma(ap, bb.x, acc[2 * q]);
                acc[2 * q + 1] = f32x2_fma(ap, bb.y, acc[2 * q + 1]);
            }
        }

        // store partials: P[g][n0+j][mrow]
        {
            float* pp = g_P + ((size_t)g * HID + n0) * BB + mrow;
#pragma unroll
            for (int q = 0; q < 16; q++) {
                float lo, hi;
                f32x2_unpack(acc[q], lo, hi);
                __stcg(pp + (size_t)(2 * q) * BB, lo);
                __stcg(pp + (size_t)(2 * q + 1) * BB, hi);
            }
        }

        grid_barrier(++epoch);

        // ---------------- phase B: reduce + tanh -> YT[t] ----------------
        {
            float* __restrict__ yrow = g_YT + ((size_t)t * HID + nb) * BB;
            const float* __restrict__ prow = g_P + (size_t)nb * BB;
#pragma unroll
            for (int i = 0; i < 4; i++) {
                int m = lane + 32 * i;
                float s = bv;
#pragma unroll
                for (int gg = 0; gg < 8; gg++)
                    s += __ldcg(prow + (size_t)gg * HID * BB + m);
                int tok = inputs[m * TT + t];
                s += Wx[(size_t)tok * HID + nb];
                __stcg(yrow + m, tanhf(s));
            }
        }

        grid_barrier(++epoch);
    }
}

// =====================================================================
// Decoder: out[t*B+m, v] = YT[t][:, m] . Wd[:, v] + bd[v]
// BM=128 (= one timestep), BN=128, BK=8, 256 threads, 8x8 micro-tile.
// Grid: (2048/128, 256) = (16, 256).
// =====================================================================
__global__ void __launch_bounds__(256, 2)
decoder_kernel(const float* __restrict__ Wd,   // [H, V]
               const float* __restrict__ bd,   // [V]
               float* __restrict__ out)        // [T*B, V]
{
    __shared__ float As[8][128];   // [k][m]
    __shared__ float Bs[8][128];   // [k][n]

    const int tid = threadIdx.x;
    const int t   = blockIdx.y;                 // timestep = row block
    const int n0  = blockIdx.x * 128;

    const int tx = tid & 15;                    // 16 col-groups of 8
    const int ty = tid >> 4;                    // 16 row-groups of 8

    const float* __restrict__ Ysrc = g_YT + (size_t)t * HID * BB;  // [k][m]

    unsigned long long acc[8][4];
#pragma unroll
    for (int i = 0; i < 8; i++)
#pragma unroll
        for (int j = 0; j < 4; j++) acc[i][j] = 0ull;

    const int lk = tid >> 5;                    // 0..7
    const int lm = (tid & 31) * 4;              // 0..124

    for (int k0 = 0; k0 < HID; k0 += 8) {
        *(float4*)&As[lk][lm] = *(const float4*)&Ysrc[(size_t)(k0 + lk) * BB + lm];
        *(float4*)&Bs[lk][lm] = *(const float4*)&Wd[(size_t)(k0 + lk) * VOCAB + n0 + lm];
        __syncthreads();

#pragma unroll
        for (int kk = 0; kk < 8; kk++) {
            float4 a0 = *(const float4*)&As[kk][ty * 8];
            float4 a1 = *(const float4*)&As[kk][ty * 8 + 4];
            ulonglong2 b0 = *(const ulonglong2*)&Bs[kk][tx * 8];
            ulonglong2 b1 = *(const ulonglong2*)&Bs[kk][tx * 8 + 4];
            unsigned long long ap[8];
            ap[0] = f32x2_pack(a0.x, a0.x);
            ap[1] = f32x2_pack(a0.y, a0.y);
            ap[2] = f32x2_pack(a0.z, a0.z);
            ap[3] = f32x2_pack(a0.w, a0.w);
            ap[4] = f32x2_pack(a1.x, a1.x);
            ap[5] = f32x2_pack(a1.y, a1.y);
            ap[6] = f32x2_pack(a1.z, a1.z);
            ap[7] = f32x2_pack(a1.w, a1.w);
#pragma unroll
            for (int i = 0; i < 8; i++) {
                acc[i][0] = f32x2_fma(ap[i], b0.x, acc[i][0]);
                acc[i][1] = f32x2_fma(ap[i], b0.y, acc[i][1]);
                acc[i][2] = f32x2_fma(ap[i], b1.x, acc[i][2]);
                acc[i][3] = f32x2_fma(ap[i], b1.y, acc[i][3]);
            }
        }
        __syncthreads();
    }

    const int nbase = n0 + tx * 8;
    float4 bd0 = *(const float4*)&bd[nbase];
    float4 bd1 = *(const float4*)&bd[nbase + 4];
#pragma unroll
    for (int i = 0; i < 8; i++) {
        const int r = t * BB + ty * 8 + i;
        float c0, c1, c2, c3, c4, c5, c6, c7;
        f32x2_unpack(acc[i][0], c0, c1);
        f32x2_unpack(acc[i][1], c2, c3);
        f32x2_unpack(acc[i][2], c4, c5);
        f32x2_unpack(acc[i][3], c6, c7);
        float4 v0 = make_float4(c0 + bd0.x, c1 + bd0.y, c2 + bd0.z, c3 + bd0.w);
        float4 v1 = make_float4(c4 + bd1.x, c5 + bd1.y, c6 + bd1.z, c7 + bd1.w);
        *(float4*)&out[(size_t)r * VOCAB + nbase]     = v0;
        *(float4*)&out[(size_t)r * VOCAB + nbase + 4] = v1;
    }
}

// h_final[m][k] = YT[T-1][k][m]
__global__ void copy_hfinal_kernel(float* __restrict__ dst) {
    int idx = blockIdx.x * 256 + threadIdx.x;
    int m = idx & (BB - 1);
    int k = idx >> 7;
    dst[(size_t)m * HID + k] = g_YT[((size_t)(TT - 1) * HID + k) * BB + m];
}

extern "C" void kernel_launch(void* const* d_in, const int* in_sizes, int n_in,
                              void* d_out, int out_size)
{
    const int*   inputs = (const int*)  d_in[0];   // (B, T) int32
    const float* state  = (const float*)d_in[1];   // (B, H)
    const float* Wx     = (const float*)d_in[2];   // (V, H)
    const float* Wh     = (const float*)d_in[3];   // (H, H)
    const float* bias   = (const float*)d_in[4];   // (H,)
    const float* Wd     = (const float*)d_in[5];   // (H, V)
    const float* bd     = (const float*)d_in[6];   // (V,)
    float* out = (float*)d_out;

    // reset barrier state + transpose initial hidden state
    init_kernel<<<(BB * HID) / 256, 256>>>(state);

    // whole recurrence in one persistent kernel (128 resident CTAs)
    rnn_persistent<<<NCTAS, 256>>>(inputs, Wx, Wh, bias);

    // decoder GEMM over all timesteps
    dim3 gridD(VOCAB / 128, TT);   // (16, 256)
    decoder_kernel<<<gridD, 256>>>(Wd, bd, out);

    // h_final at the tail of the flattened output tuple
    size_t hf_off = (size_t)out_size - (size_t)BB * HID;
    copy_hfinal_kernel<<<(BB * HID) / 256, 256>>>(out + hf_off);
}

// round 4
// speedup vs baseline: 2.4827x; 1.4074x over previous
#include <cuda_runtime.h>
#include <cuda_bf16.h>
#include <cstdint>

#define VOCAB 2048
#define HID   1024
#define TT    256
#define BB    128
#define NCTAS 256          // recurrence CTAs (2 per SM, all resident)

// ---- persistent scratch (static device allocations are allowed) ----
__device__ __align__(128) float         g_YT[(size_t)TT * HID * BB];   // [t][k][m] fp32, 128 MB
__device__ __align__(128) float         g_h0T[HID * BB];               // transposed initial state
__device__ __align__(128) float         g_P[8u * HID * BB];            // k-split partials [g][n][m], 4 MB
__device__ __align__(128) __nv_bfloat16 g_Yhi[(size_t)TT * BB * HID];  // [t*B][k] hi plane, 64 MB
__device__ __align__(128) __nv_bfloat16 g_Ylo[(size_t)TT * BB * HID];  // lo plane, 64 MB
__device__ __align__(128) __nv_bfloat16 g_Bhi[(size_t)VOCAB * HID];    // WdT hi [n][k], 4 MB
__device__ __align__(128) __nv_bfloat16 g_Blo[(size_t)VOCAB * HID];    // WdT lo [n][k], 4 MB
__device__ unsigned g_cnt;                                             // barrier arrival counter
__device__ unsigned g_phase;                                           // barrier release phase

// ---------------- f32x2 helpers (FFMA2: 2 MACs per issue) ----------------
__device__ __forceinline__ unsigned long long f32x2_pack(float lo, float hi) {
    unsigned long long r;
    asm("mov.b64 %0, {%1, %2};" : "=l"(r) : "f"(lo), "f"(hi));
    return r;
}
__device__ __forceinline__ unsigned long long f32x2_fma(unsigned long long a,
                                                        unsigned long long b,
                                                        unsigned long long c) {
    unsigned long long d;
    asm("fma.rn.f32x2 %0, %1, %2, %3;" : "=l"(d) : "l"(a), "l"(b), "l"(c));
    return d;
}
__device__ __forceinline__ void f32x2_unpack(unsigned long long v, float& lo, float& hi) {
    asm("mov.b64 {%0, %1}, %2;" : "=f"(lo), "=f"(hi) : "l"(v));
}

// ---------------- smem/async helpers ----------------
__device__ __forceinline__ uint32_t smem_u32(const void* p) {
    uint32_t a;
    asm("{ .reg .u64 t; cvta.to.shared.u64 t, %1; cvt.u32.u64 %0, t; }" : "=r"(a) : "l"(p));
    return a;
}
__device__ __forceinline__ void cp_async16(uint32_t sdst, const void* gsrc) {
    asm volatile("cp.async.cg.shared.global [%0], [%1], 16;" :: "r"(sdst), "l"(gsrc));
}
#define CP_COMMIT()  asm volatile("cp.async.commit_group;" ::: "memory")
#define CP_WAIT1()   asm volatile("cp.async.wait_group 1;" ::: "memory")

__device__ __forceinline__ void ldsm_x4(uint32_t r[4], uint32_t addr) {
    asm volatile("ldmatrix.sync.aligned.m8n8.x4.shared.b16 {%0,%1,%2,%3}, [%4];"
                 : "=r"(r[0]), "=r"(r[1]), "=r"(r[2]), "=r"(r[3]) : "r"(addr));
}
__device__ __forceinline__ void mma16816(float d[4], const uint32_t a[4], const uint32_t b0,
                                         const uint32_t b1) {
    asm volatile(
        "mma.sync.aligned.m16n8k16.row.col.f32.bf16.bf16.f32 "
        "{%0,%1,%2,%3}, {%4,%5,%6,%7}, {%8,%9}, {%0,%1,%2,%3};"
        : "+f"(d[0]), "+f"(d[1]), "+f"(d[2]), "+f"(d[3])
        : "r"(a[0]), "r"(a[1]), "r"(a[2]), "r"(a[3]), "r"(b0), "r"(b1));
}

// ---------------- grid barrier (NCTAS CTAs, all resident) ----------------
__device__ __forceinline__ void grid_barrier(unsigned epoch) {
    __syncthreads();                 // intra-CTA HB; release below publishes all
    if (threadIdx.x == 0) {
        unsigned old;
        asm volatile("atom.add.acq_rel.gpu.u32 %0, [%1], 1;"
                     : "=r"(old) : "l"(&g_cnt) : "memory");
        if (old == epoch * (unsigned)NCTAS - 1u) {
            asm volatile("st.release.gpu.u32 [%0], %1;" :: "l"(&g_phase), "r"(epoch) : "memory");
        } else {
            unsigned cur;
            do {
                asm volatile("ld.acquire.gpu.u32 %0, [%1];" : "=r"(cur) : "l"(&g_phase) : "memory");
                if (cur < epoch) __nanosleep(32);
            } while (cur < epoch);
        }
    }
    __syncthreads();
}

// ---------------- init: reset barrier + transpose initial state ----------------
__global__ void init_kernel(const float* __restrict__ state) {
    if (blockIdx.x == 0 && threadIdx.x == 0) { g_cnt = 0u; g_phase = 0u; }
    int idx = blockIdx.x * 256 + threadIdx.x;
    int m = idx & (BB - 1);
    int k = idx >> 7;
    g_h0T[k * BB + m] = state[(size_t)m * HID + k];
}

// ---------------- Wd prep: transpose + bf16 hi/lo split planes ----------------
__global__ void __launch_bounds__(256)
wd_prep(const float* __restrict__ Wd) {
    __shared__ float ts[32][33];
    const int n0 = blockIdx.x * 32, k0 = blockIdx.y * 32;
    const int tx = threadIdx.x & 31, ty = threadIdx.x >> 5;
#pragma unroll
    for (int j = 0; j < 4; j++)
        ts[ty + 8 * j][tx] = Wd[(size_t)(k0 + ty + 8 * j) * VOCAB + n0 + tx];
    __syncthreads();
#pragma unroll
    for (int j = 0; j < 4; j++) {
        float v = ts[tx][ty + 8 * j];
        __nv_bfloat16 h = __float2bfloat16_rn(v);
        __nv_bfloat16 l = __float2bfloat16_rn(v - __bfloat162float(h));
        size_t o = (size_t)(n0 + ty + 8 * j) * HID + k0 + tx;
        g_Bhi[o] = h;
        g_Blo[o] = l;
    }
}

// ---------------- Y prep: YT fp32 [t][k][m] -> Yhi/Ylo bf16 [t*B+m][k] ----------------
__global__ void __launch_bounds__(256)
y_prep() {
    __shared__ float ts[64][33];
    const int t  = blockIdx.z;
    const int k0 = blockIdx.x * 64;
    const int m0 = blockIdx.y * 32;
    const int lane = threadIdx.x & 31, w = threadIdx.x >> 5;
#pragma unroll
    for (int j = 0; j < 8; j++) {
        int kr = w + 8 * j;
        ts[kr][lane] = g_YT[((size_t)t * HID + k0 + kr) * BB + m0 + lane];
    }
    __syncthreads();
#pragma unroll
    for (int j = 0; j < 4; j++) {
        int m = w + 8 * j;
        int kk = lane * 2;
        float v0 = ts[kk][m], v1 = ts[kk + 1][m];
        __nv_bfloat16 h0 = __float2bfloat16_rn(v0);
        __nv_bfloat16 h1 = __float2bfloat16_rn(v1);
        __nv_bfloat16 l0 = __float2bfloat16_rn(v0 - __bfloat162float(h0));
        __nv_bfloat16 l1 = __float2bfloat16_rn(v1 - __bfloat162float(h1));
        size_t o = (size_t)(t * BB + m0 + m) * HID + k0 + kk;
        uint32_t hp = (uint32_t)__bfloat16_as_ushort(h0) | ((uint32_t)__bfloat16_as_ushort(h1) << 16);
        uint32_t lp = (uint32_t)__bfloat16_as_ushort(l0) | ((uint32_t)__bfloat16_as_ushort(l1) << 16);
        *(uint32_t*)&g_Yhi[o] = hp;
        *(uint32_t*)&g_Ylo[o] = lp;
    }
}

// =====================================================================
// Persistent recurrence, 256 CTAs x 256 threads (2 CTAs/SM).
// CTA (kg 0..7, cg 0..31): k-range kg*128 (full, per thread), cols cg*32.
// 8 partial groups. Thread: 1 m-row x 16 cols x 128 k.
// =====================================================================
__global__ void __launch_bounds__(256, 2)
rnn_persistent(const int*   __restrict__ inputs,   // [B, T]
               const float* __restrict__ Wx,       // [V, H]
               const float* __restrict__ Wh,       // [H, H]
               const float* __restrict__ bias)     // [H]
{
    __shared__ float Whs[128][32];

    const int tid = threadIdx.x;
    const int cta = blockIdx.x;                    // 0..255
    const int cg  = cta & 31;
    const int kg  = cta >> 5;                      // 0..7
    const int n0  = cg * 32;
    const int ks  = kg * 128;

    for (int i = tid; i < 128 * 32; i += 256) {
        int kk = i >> 5, nn = i & 31;
        Whs[kk][nn] = Wh[(size_t)(ks + kk) * HID + n0 + nn];
    }
    __syncthreads();

    const int warp  = tid >> 5;
    const int lane  = tid & 31;
    const int mrow  = (warp & 3) * 32 + lane;
    const int chalf = warp >> 2;                   // 0/1: col half (16 cols)
    const int nc0   = chalf * 16;

    const int nb    = cta * 4 + (warp >> 1);       // phase-B column 0..1023
    const int mhalf = warp & 1;
    const float bv  = bias[nb];

    unsigned epoch = 0;

    for (int t = 0; t < TT; t++) {
        const float* __restrict__ hT =
            (t == 0) ? g_h0T : (g_YT + (size_t)(t - 1) * HID * BB);

        // ---------------- phase A: partial GEMM (128 k x 16 cols per thread) ----------------
        unsigned long long acc[8];
#pragma unroll
        for (int j = 0; j < 8; j++) acc[j] = 0ull;

        const float* __restrict__ hp = hT + (size_t)ks * BB + mrow;

#pragma unroll 8
        for (int k = 0; k < 128; k++) {
            float a = __ldcg(hp + (size_t)k * BB);
            unsigned long long ap = f32x2_pack(a, a);
            const ulonglong2* wr = (const ulonglong2*)&Whs[k][nc0];
            ulonglong2 w0 = wr[0], w1 = wr[1];
            acc[0] = f32x2_fma(ap, w0.x, acc[0]);
            acc[1] = f32x2_fma(ap, w0.y, acc[1]);
            acc[2] = f32x2_fma(ap, w1.x, acc[2]);
            acc[3] = f32x2_fma(ap, w1.y, acc[3]);
            ulonglong2 w2 = wr[2], w3 = wr[3];
            acc[4] = f32x2_fma(ap, w2.x, acc[4]);
            acc[5] = f32x2_fma(ap, w2.y, acc[5]);
            acc[6] = f32x2_fma(ap, w3.x, acc[6]);
            acc[7] = f32x2_fma(ap, w3.y, acc[7]);
        }

        {
            float* pp = g_P + ((size_t)kg * HID + n0 + nc0) * BB + mrow;
#pragma unroll
            for (int q = 0; q < 8; q++) {
                float lo, hi;
                f32x2_unpack(acc[q], lo, hi);
                __stcg(pp + (size_t)(2 * q) * BB, lo);
                __stcg(pp + (size_t)(2 * q + 1) * BB, hi);
            }
        }

        grid_barrier(++epoch);

        // ---------------- phase B: reduce 8 partials + tanh -> YT[t] ----------------
        {
            float* __restrict__ yrow = g_YT + ((size_t)t * HID + nb) * BB;
            const float* __restrict__ prow = g_P + (size_t)nb * BB;
#pragma unroll
            for (int mi = 0; mi < 2; mi++) {
                int m = mhalf * 64 + mi * 32 + lane;
                float s = bv;
#pragma unroll
                for (int gg = 0; gg < 8; gg++)
                    s += __ldcg(prow + (size_t)gg * HID * BB + m);
                int tok = inputs[m * TT + t];
                s += Wx[(size_t)tok * HID + nb];
                __stcg(yrow + m, tanhf(s));
            }
        }

        grid_barrier(++epoch);
    }
}

// =====================================================================
// Decoder on mma.sync bf16 (2-term split: Ah*Bh + Ah*Bl + Al*Bh).
// BM=128, BN=128, BK=64, 256 thr (8 warps, 2m x 4n grid of 64x32 tiles).
// cp.async double-buffered: per stage Ah 16K | Al 16K | Bh 16K | Bl 16K = 64KB.
// =====================================================================
#define DEC_STAGE 65536
#define DEC_SMEM  (2 * DEC_STAGE)

__global__ void __launch_bounds__(256, 1)
decoder_mma(const float* __restrict__ bd, float* __restrict__ out)
{
    extern __shared__ __align__(128) char dsm[];
    const uint32_t sbase = smem_u32(dsm);

    const int tid  = threadIdx.x;
    const int lane = tid & 31;
    const int wid  = tid >> 5;
    const int wm   = wid >> 2;          // 0..1
    const int wn   = wid & 3;           // 0..3
    const int mblk = blockIdx.y;        // 0..255 (= timestep)
    const int n0g  = blockIdx.x * 128;  // global n offset

    const __nv_bfloat16* __restrict__ gAh = g_Yhi + (size_t)mblk * 128 * HID;
    const __nv_bfloat16* __restrict__ gAl = g_Ylo + (size_t)mblk * 128 * HID;
    const __nv_bfloat16* __restrict__ gBh = g_Bhi + (size_t)n0g * HID;
    const __nv_bfloat16* __restrict__ gBl = g_Blo + (size_t)n0g * HID;

    // copy-in assignment: 4 chunks of 16B per plane per thread
    // chunk c (0..1023): row = c>>3, cx = c&7; smem off = row*128 + ((cx*16) ^ ((row&7)<<4))
    auto issue_stage = [&](int stage, int k0) {
        const uint32_t sb = sbase + stage * DEC_STAGE;
#pragma unroll
        for (int j = 0; j < 4; j++) {
            int c   = tid + 256 * j;
            int row = c >> 3, cx = c & 7;
            uint32_t soff = (uint32_t)(row * 128 + ((cx * 16) ^ ((row & 7) << 4)));
            size_t goff = (size_t)row * HID + k0 + cx * 8;
            cp_async16(sb + soff,         gAh + goff);
            cp_async16(sb + 16384 + soff, gAl + goff);
            cp_async16(sb + 32768 + soff, gBh + goff);
            cp_async16(sb + 49152 + soff, gBl + goff);
        }
    };

    // per-lane ldmatrix address components
    const int roffA = (lane & 7) + ((lane >> 3) & 1) * 8;
    const int kaddA = (lane >> 4) & 1;
    const int roffB = (lane & 7) + ((lane >> 4) & 1) * 8;
    const int kaddB = (lane >> 3) & 1;
    const int swx   = (lane & 7) << 4;
    const uint32_t rowA = (uint32_t)((wm * 64 + roffA) * 128);
    const uint32_t rowB = (uint32_t)((wn * 32 + roffB) * 128);

    float acc[4][4][4];
#pragma unroll
    for (int i = 0; i < 4; i++)
#pragma unroll
        for (int j = 0; j < 4; j++)
#pragma unroll
            for (int q = 0; q < 4; q++) acc[i][j][q] = 0.f;

    issue_stage(0, 0);
    CP_COMMIT();

    for (int it = 0; it < 16; it++) {
        if (it + 1 < 16) issue_stage((it + 1) & 1, (it + 1) * 64);
        CP_COMMIT();
        CP_WAIT1();
        __syncthreads();

        const uint32_t sb = sbase + (it & 1) * DEC_STAGE;
        const uint32_t pAh = sb,          pAl = sb + 16384;
        const uint32_t pBh = sb + 32768,  pBl = sb + 49152;

#pragma unroll
        for (int kk = 0; kk < 4; kk++) {
            const uint32_t kA = (uint32_t)((kk * 32 + kaddA * 16) ^ swx);
            const uint32_t kB = (uint32_t)((kk * 32 + kaddB * 16) ^ swx);

            uint32_t ah[4][4], al[4][4];
#pragma unroll
            for (int mt = 0; mt < 4; mt++) {
                ldsm_x4(ah[mt], pAh + rowA + mt * 2048 + kA);
                ldsm_x4(al[mt], pAl + rowA + mt * 2048 + kA);
            }
            uint32_t bh[2][4], bl[2][4];
#pragma unroll
            for (int np = 0; np < 2; np++) {
                ldsm_x4(bh[np], pBh + rowB + np * 2048 + kB);
                ldsm_x4(bl[np], pBl + rowB + np * 2048 + kB);
            }
#pragma unroll
            for (int mt = 0; mt < 4; mt++) {
#pragma unroll
                for (int nt = 0; nt < 4; nt++) {
                    const int np = nt >> 1, ni = (nt & 1) * 2;
                    mma16816(acc[mt][nt], ah[mt], bh[np][ni], bh[np][ni + 1]);
                    mma16816(acc[mt][nt], ah[mt], bl[np][ni], bl[np][ni + 1]);
                    mma16816(acc[mt][nt], al[mt], bh[np][ni], bh[np][ni + 1]);
                }
            }
        }
        __syncthreads();
    }

    // epilogue: d0,d1 -> (row, col..col+1); d2,d3 -> (row+8, ...)
    const int rbase = mblk * 128 + wm * 64 + (lane >> 2);
    const int cbase = n0g + wn * 32 + (lane & 3) * 2;
#pragma unroll
    for (int mt = 0; mt < 4; mt++) {
#pragma unroll
        for (int nt = 0; nt < 4; nt++) {
            const int col = cbase + nt * 8;
            const float2 bv = *(const float2*)&bd[col];
            const int r0 = rbase + mt * 16;
            float2 v0 = make_float2(acc[mt][nt][0] + bv.x, acc[mt][nt][1] + bv.y);
            float2 v1 = make_float2(acc[mt][nt][2] + bv.x, acc[mt][nt][3] + bv.y);
            *(float2*)&out[(size_t)r0 * VOCAB + col]       = v0;
            *(float2*)&out[(size_t)(r0 + 8) * VOCAB + col] = v1;
        }
    }
}

// h_final[m][k] = YT[T-1][k][m]
__global__ void copy_hfinal_kernel(float* __restrict__ dst) {
    int idx = blockIdx.x * 256 + threadIdx.x;
    int m = idx & (BB - 1);
    int k = idx >> 7;
    dst[(size_t)m * HID + k] = g_YT[((size_t)(TT - 1) * HID + k) * BB + m];
}

extern "C" void kernel_launch(void* const* d_in, const int* in_sizes, int n_in,
                              void* d_out, int out_size)
{
    const int*   inputs = (const int*)  d_in[0];
    const float* state  = (const float*)d_in[1];
    const float* Wx     = (const float*)d_in[2];
    const float* Wh     = (const float*)d_in[3];
    const float* bias   = (const float*)d_in[4];
    const float* Wd     = (const float*)d_in[5];
    const float* bd     = (const float*)d_in[6];
    float* out = (float*)d_out;

    cudaFuncSetAttribute(decoder_mma, cudaFuncAttributeMaxDynamicSharedMemorySize, DEC_SMEM);

    init_kernel<<<(BB * HID) / 256, 256>>>(state);

    dim3 gridW(VOCAB / 32, HID / 32);
    wd_prep<<<gridW, 256>>>(Wd);

    rnn_persistent<<<NCTAS, 256>>>(inputs, Wx, Wh, bias);

    dim3 gridY(HID / 64, BB / 32, TT);
    y_prep<<<gridY, 256>>>();

    dim3 gridD(VOCAB / 128, TT);   // (16, 256)
    decoder_mma<<<gridD, 256, DEC_SMEM>>>(bd, out);

    size_t hf_off = (size_t)out_size - (size_t)BB * HID;
    copy_hfinal_kernel<<<(BB * HID) / 256, 256>>>(out + hf_off);
}